// round 2
// baseline (speedup 1.0000x reference)
#include <cuda_runtime.h>
#include <math.h>

// ---------------- static device scratch ----------------
__device__ float g_A[64u*256u*32u*32u];
__device__ float g_B[64u*256u*32u*32u];
__device__ float g_H0[64u*256u*16u*16u];
__device__ float g_SC[64u*256u*16u*16u];
__device__ float g_T8[64u*256u*8u*8u];
__device__ float g_H1[64u*256u*8u*8u];
__device__ float g_H2[64u*256u*8u*8u];
__device__ float g_H3[64u*256u*8u*8u];
__device__ float g_PX[64u*3u*16u*16u];

__device__ float g_sw0[6912];     // b0_w1  [(c*9+k)][256]
__device__ float g_sw1[589824];   // b0_w2
__device__ float g_sw2[768];      // b0_wsc [c][256]
__device__ float g_sw3[589824];   // b1_w1
__device__ float g_sw4[589824];   // b1_w2
__device__ float g_sw5[65536];    // b1_wsc
__device__ float g_sw6[589824];   // b2_w1
__device__ float g_sw7[589824];   // b2_w2
__device__ float g_sw8[589824];   // b3_w1
__device__ float g_sw9[589824];   // b3_w2
__device__ float g_swlin[256];
__device__ float g_swemb[25600];

__device__ float g_sigma[12];
__device__ float g_enorm[1024];
__device__ float2 g_cand[16384*16];
__device__ float g_xnorm[16384];
__device__ float g_md[16384];
__device__ int   g_ind[16384];
__device__ float g_qloss[64];
__device__ int   g_hist[1024];
__device__ float g_hf[64*256];

// ---------------- spectral norm ----------------
struct SnDesc { const float* w; float* out; int O; int R; int transpose; };
struct SnArgs { SnDesc d[12]; };

__global__ void init_zero_k() {
    int i = blockIdx.x * blockDim.x + threadIdx.x;
    if (i < 1024) g_hist[i] = 0;
    if (i < 64)   g_qloss[i] = 0.f;
}

__global__ void sn_sigma_k(SnArgs a) {
    __shared__ float sv[2304];
    __shared__ float red[256];
    const SnDesc d = a.d[blockIdx.x];
    const float* W = d.w;
    const int O = d.O, R = d.R, tid = threadIdx.x;
    const float is = rsqrtf((float)O);
    for (int j = tid; j < R; j += 256) {
        float s = 0.f;
        for (int i = 0; i < O; i++) s += W[(size_t)i * R + j];
        sv[j] = s * is;
    }
    __syncthreads();
    float loc = 0.f;
    for (int j = tid; j < R; j += 256) { float v = sv[j]; loc += v * v; }
    red[tid] = loc; __syncthreads();
    for (int s = 128; s > 0; s >>= 1) { if (tid < s) red[tid] += red[tid + s]; __syncthreads(); }
    const float fv = 1.f / (sqrtf(red[0]) + 1e-8f);
    __syncthreads();
    loc = 0.f;
    for (int i = tid; i < O; i += 256) {
        float t = 0.f;
        const float* row = W + (size_t)i * R;
        for (int j = 0; j < R; j++) t += row[j] * sv[j];
        t *= fv; loc += t * t;
    }
    red[tid] = loc; __syncthreads();
    for (int s = 128; s > 0; s >>= 1) { if (tid < s) red[tid] += red[tid + s]; __syncthreads(); }
    if (tid == 0) g_sigma[blockIdx.x] = red[0] / (sqrtf(red[0]) + 1e-8f);
}

__global__ void sn_scale_k(SnArgs a) {
    const SnDesc d = a.d[blockIdx.x];
    const float inv = 1.f / g_sigma[blockIdx.x];
    const int n = d.O * d.R, stride = gridDim.y * blockDim.x;
    for (int e = blockIdx.y * blockDim.x + threadIdx.x; e < n; e += stride) {
        float v = d.w[e] * inv;
        if (d.transpose) { int o = e / d.R, rr = e % d.R; d.out[(size_t)rr * d.O + o] = v; }
        else d.out[e] = v;
    }
}

// ---------------- conv3x3 pad1: 8 warps = 64 out-ch, 32 lanes x 4 px ----------------
template<int TH, int TW, int G>
__global__ void __launch_bounds__(256) conv3x3_k(
    const float* __restrict__ in, const float* __restrict__ wt,
    const float* __restrict__ bias, const float* __restrict__ res,
    float* __restrict__ out, int C, int O, int H, int W, int relu_in)
{
    constexpr int PH = TH + 2, PW = TW + 4, XG = TW / 4;
    __shared__ float s_in[G * PH * PW];
    __shared__ float s_w[768];
    const int tid = threadIdx.x, ot = tid >> 5, pt = tid & 31;
    const int g = pt / (TH * XG), r = pt % (TH * XG), row = r / XG, xg = r % XG;
    const int tilesX = W / TW;
    const int tileY = blockIdx.y / tilesX, tileX = blockIdx.y % tilesX;
    const int img = blockIdx.z * G + g, obase = blockIdx.x * 64;

    float acc[8][4];
#pragma unroll
    for (int a = 0; a < 8; a++) { acc[a][0]=acc[a][1]=acc[a][2]=acc[a][3]=0.f; }

    for (int c = 0; c < C; c++) {
        __syncthreads();
        for (int idx = tid; idx < G * PH * (TW + 2); idx += 256) {
            int gg = idx / (PH * (TW + 2));
            int r2 = idx % (PH * (TW + 2));
            int py = r2 / (TW + 2), px = r2 % (TW + 2);
            int gy = tileY * TH + py - 1, gx = tileX * TW + px - 1;
            float v = 0.f;
            if ((unsigned)gy < (unsigned)H && (unsigned)gx < (unsigned)W)
                v = in[(((size_t)(blockIdx.z * G + gg) * C + c) * H + gy) * W + gx];
            if (relu_in) v = fmaxf(v, 0.f);
            s_in[gg * PH * PW + py * PW + px] = v;
        }
        for (int idx = tid; idx < 576; idx += 256) {
            int k = idx >> 6, o = idx & 63;
            s_w[o * 12 + k] = wt[((size_t)c * 9 + k) * O + obase + o];
        }
        __syncthreads();

        float w[8][9];
#pragma unroll
        for (int oo = 0; oo < 8; oo++) {
            const float* wp = &s_w[(oo * 8 + ot) * 12];
            float4 a4 = *(const float4*)wp;
            float4 b4 = *(const float4*)(wp + 4);
            w[oo][0]=a4.x; w[oo][1]=a4.y; w[oo][2]=a4.z; w[oo][3]=a4.w;
            w[oo][4]=b4.x; w[oo][5]=b4.y; w[oo][6]=b4.z; w[oo][7]=b4.w;
            w[oo][8]=wp[8];
        }
        const float* sp = &s_in[g * PH * PW + row * PW + xg * 4];
#pragma unroll
        for (int dy = 0; dy < 3; dy++) {
            float iv[6];
#pragma unroll
            for (int xx = 0; xx < 6; xx++) iv[xx] = sp[dy * PW + xx];
#pragma unroll
            for (int dx = 0; dx < 3; dx++)
#pragma unroll
                for (int oo = 0; oo < 8; oo++) {
                    float ww = w[oo][dy * 3 + dx];
                    acc[oo][0] += ww * iv[dx];     acc[oo][1] += ww * iv[dx + 1];
                    acc[oo][2] += ww * iv[dx + 2]; acc[oo][3] += ww * iv[dx + 3];
                }
        }
    }
    const int y = tileY * TH + row, x = tileX * TW + xg * 4;
#pragma unroll
    for (int oo = 0; oo < 8; oo++) {
        int o = obase + oo * 8 + ot;
        size_t base = (((size_t)img * O + o) * H + y) * W + x;
        float b = bias[o];
        float4 v = { acc[oo][0] + b, acc[oo][1] + b, acc[oo][2] + b, acc[oo][3] + b };
        if (res) {
            float4 r4 = *reinterpret_cast<const float4*>(res + base);
            v.x += r4.x; v.y += r4.y; v.z += r4.z; v.w += r4.w;
        }
        *reinterpret_cast<float4*>(out + base) = v;
    }
}

// ---------------- conv1x1 ----------------
__global__ void __launch_bounds__(256) conv1x1_k(
    const float* __restrict__ in, const float* __restrict__ wt,
    const float* __restrict__ bias, float* __restrict__ out, int C, int O, int HW)
{
    __shared__ __align__(16) float s_x[128];
    __shared__ float s_w1[64];
    const int tid = threadIdx.x, ot = tid >> 5, pt = tid & 31;
    const int obase = blockIdx.x * 64, pbase = blockIdx.y * 128;
    float acc[8][4];
#pragma unroll
    for (int a = 0; a < 8; a++) { acc[a][0]=acc[a][1]=acc[a][2]=acc[a][3]=0.f; }
    for (int c = 0; c < C; c++) {
        __syncthreads();
        if (tid < 128) {
            int p = pbase + tid, b = p / HW, hw = p % HW;
            s_x[tid] = in[((size_t)b * C + c) * HW + hw];
        } else if (tid < 192) s_w1[tid - 128] = wt[(size_t)c * O + obase + (tid - 128)];
        __syncthreads();
        float4 xv = *reinterpret_cast<const float4*>(&s_x[pt * 4]);
#pragma unroll
        for (int oo = 0; oo < 8; oo++) {
            float w = s_w1[oo * 8 + ot];
            acc[oo][0] += w * xv.x; acc[oo][1] += w * xv.y;
            acc[oo][2] += w * xv.z; acc[oo][3] += w * xv.w;
        }
    }
    int p = pbase + pt * 4, b = p / HW, hw = p % HW;
#pragma unroll
    for (int oo = 0; oo < 8; oo++) {
        int o = obase + oo * 8 + ot;
        float bb = bias[o];
        float4 v = { acc[oo][0] + bb, acc[oo][1] + bb, acc[oo][2] + bb, acc[oo][3] + bb };
        *reinterpret_cast<float4*>(out + ((size_t)b * O + o) * HW + hw) = v;
    }
}

// ---------------- avgpool 2x2 (+res) ----------------
__global__ void pool_k(const float* __restrict__ in, const float* __restrict__ res,
                       float* __restrict__ out, int total, int OH, int OW)
{
    int idx = blockIdx.x * blockDim.x + threadIdx.x;
    if (idx >= total) return;
    int ow = idx % OW, t = idx / OW, oh = t % OH, bc = t / OH;
    int IW = OW * 2;
    size_t base = (((size_t)bc * (OH * 2)) + oh * 2) * IW + ow * 2;
    float v = 0.25f * (in[base] + in[base + 1] + in[base + IW] + in[base + IW + 1]);
    if (res) v += res[idx];
    out[idx] = v;
}

// ---------------- VQ ----------------
__global__ void enorm_k(const float* __restrict__ cb) {
    int k = blockIdx.x * blockDim.x + threadIdx.x;
    if (k >= 1024) return;
    float s = 0.f;
    for (int c = 0; c < 256; c++) { float v = cb[(size_t)c * 1024 + k]; s += v * v; }
    g_enorm[k] = s;
}

__global__ void xnorm_k(const float* __restrict__ h, int C, int HW) {
    int b = blockIdx.x;
    for (int hw = threadIdx.x; hw < HW; hw += blockDim.x) {
        float s = 0.f;
        for (int c = 0; c < C; c++) { float v = h[((size_t)b * C + c) * HW + hw]; s += v * v; }
        g_xnorm[b * HW + hw] = s;
    }
}

__global__ void __launch_bounds__(256) vq_pass1_k(
    const float* __restrict__ h, const float* __restrict__ cb, int C, int HW, int K)
{
    __shared__ __align__(16) float s_x[128];
    __shared__ float s_e[64];
    __shared__ float s_bv[1024];
    __shared__ int   s_bi[1024];
    const int tid = threadIdx.x, ot = tid >> 5, pt = tid & 31;
    const int ktile = blockIdx.x, pbase = blockIdx.y * 128;
    float acc[8][4];
#pragma unroll
    for (int kk = 0; kk < 8; kk++) {
        float e = -0.5f * g_enorm[ktile * 64 + kk * 8 + ot];
        acc[kk][0]=acc[kk][1]=acc[kk][2]=acc[kk][3]=e;
    }
    for (int c = 0; c < C; c++) {
        __syncthreads();
        if (tid < 128) {
            int p = pbase + tid, b = p / HW, hw = p % HW;
            s_x[tid] = h[((size_t)b * C + c) * HW + hw];
        } else if (tid < 192) s_e[tid - 128] = cb[(size_t)c * K + ktile * 64 + (tid - 128)];
        __syncthreads();
        float4 xv = *reinterpret_cast<const float4*>(&s_x[pt * 4]);
#pragma unroll
        for (int kk = 0; kk < 8; kk++) {
            float w = s_e[kk * 8 + ot];
            acc[kk][0] += w * xv.x; acc[kk][1] += w * xv.y;
            acc[kk][2] += w * xv.z; acc[kk][3] += w * xv.w;
        }
    }
    __syncthreads();
#pragma unroll
    for (int pp = 0; pp < 4; pp++) {
        float bv = acc[0][pp]; int bi = ktile * 64 + ot;
#pragma unroll
        for (int kk = 1; kk < 8; kk++)
            if (acc[kk][pp] > bv) { bv = acc[kk][pp]; bi = ktile * 64 + kk * 8 + ot; }
        s_bv[pp * 256 + tid] = bv; s_bi[pp * 256 + tid] = bi;
    }
    __syncthreads();
    if (tid < 32) {
#pragma unroll
        for (int pp = 0; pp < 4; pp++) {
            float bv = s_bv[pp * 256 + tid]; int bi = s_bi[pp * 256 + tid];
            for (int o2 = 1; o2 < 8; o2++) {
                float v = s_bv[pp * 256 + o2 * 32 + tid];
                if (v > bv) { bv = v; bi = s_bi[pp * 256 + o2 * 32 + tid]; }
            }
            int p = pbase + tid * 4 + pp;
            g_cand[(size_t)p * 16 + ktile] = make_float2(bv, __int_as_float(bi));
        }
    }
}

__global__ void vq_pass2_k(int N) {
    int n = blockIdx.x * blockDim.x + threadIdx.x;
    if (n >= N) return;
    float2 c0 = g_cand[(size_t)n * 16];
    float bv = c0.x; int bi = __float_as_int(c0.y);
    for (int t = 1; t < 16; t++) {
        float2 ct = g_cand[(size_t)n * 16 + t];
        if (ct.x > bv) { bv = ct.x; bi = __float_as_int(ct.y); }
    }
    g_md[n] = g_xnorm[n] - 2.f * bv;
    g_ind[n] = bi;
}

__global__ void vq_hist_k(int N) {
    int n = blockIdx.x * blockDim.x + threadIdx.x;
    if (n < N) atomicAdd(&g_hist[g_ind[n]], 1);
}

__global__ void vq_reduce_k(int HW, int C) {
    __shared__ float red[256];
    int b = blockIdx.x;
    float s = 0.f;
    for (int hw = threadIdx.x; hw < HW; hw += 256) s += g_md[b * HW + hw];
    red[threadIdx.x] = s; __syncthreads();
    for (int st = 128; st > 0; st >>= 1) {
        if (threadIdx.x < st) red[threadIdx.x] += red[threadIdx.x + st];
        __syncthreads();
    }
    if (threadIdx.x == 0) g_qloss[b] += 0.5f * red[0] / ((float)HW * (float)C);
}

__global__ void ppl_k(float* __restrict__ dout, int N) {
    __shared__ float red[256];
    float s = 0.f;
    for (int k = threadIdx.x; k < 1024; k += 256) {
        float p = (float)g_hist[k] / (float)N;
        s += p * logf(p + 1e-10f);
    }
    red[threadIdx.x] = s; __syncthreads();
    for (int st = 128; st > 0; st >>= 1) {
        if (threadIdx.x < st) red[threadIdx.x] += red[threadIdx.x + st];
        __syncthreads();
    }
    if (threadIdx.x == 0) dout[128] = expf(-red[0]);
}

// ---------------- head ----------------
__global__ void hf_k(const float* __restrict__ h) {
    int idx = blockIdx.x * blockDim.x + threadIdx.x;
    if (idx >= 64 * 256) return;
    const float* p = h + (size_t)idx * 64;
    float s = 0.f;
    for (int i = 0; i < 64; i++) s += fmaxf(p[i], 0.f);
    g_hf[idx] = s;
}

__global__ void final_k(const int* __restrict__ y, const float* __restrict__ lin_b,
                        float* __restrict__ dout) {
    __shared__ float red[256];
    int b = blockIdx.x, c = threadIdx.x;
    float v = g_hf[b * 256 + c];
    red[c] = v * g_swlin[c] + v * g_swemb[(size_t)y[b] * 256 + c];
    __syncthreads();
    for (int st = 128; st > 0; st >>= 1) {
        if (c < st) red[c] += red[c + st];
        __syncthreads();
    }
    if (c == 0) { dout[b] = red[0] + lin_b[0]; dout[64 + b] = g_qloss[b]; }
}

// ---------------- host ----------------
template <typename T> static T* sym(const void* s) {
    void* p = nullptr; cudaGetSymbolAddress(&p, s); return (T*)p;
}
#define SYM(x) ([]{ void* p=nullptr; cudaGetSymbolAddress(&p, x); return (float*)p; }())

extern "C" void kernel_launch(void* const* d_in, const int* in_sizes, int n_in,
                              void* d_out, int out_size) {
    (void)in_sizes; (void)n_in; (void)out_size;
    const float* x      = (const float*)d_in[0];
    const int*   y      = (const int*)d_in[1];
    const float* w_raw[12] = {
        (const float*)d_in[2],  (const float*)d_in[4],  (const float*)d_in[6],
        (const float*)d_in[8],  (const float*)d_in[10], (const float*)d_in[12],
        (const float*)d_in[14], (const float*)d_in[16], (const float*)d_in[18],
        (const float*)d_in[20], (const float*)d_in[26], (const float*)d_in[28] };
    const float* b0_b1 = (const float*)d_in[3],  *b0_b2 = (const float*)d_in[5];
    const float* b0_bsc= (const float*)d_in[7],  *b1_b1 = (const float*)d_in[9];
    const float* b1_b2 = (const float*)d_in[11], *b1_bsc= (const float*)d_in[13];
    const float* b2_b1 = (const float*)d_in[15], *b2_b2 = (const float*)d_in[17];
    const float* b3_b1 = (const float*)d_in[19], *b3_b2 = (const float*)d_in[21];
    const float* cb0 = (const float*)d_in[22], *cb1 = (const float*)d_in[23];
    const float* cb2 = (const float*)d_in[24], *cb3 = (const float*)d_in[25];
    const float* lin_b = (const float*)d_in[27];
    float* dout = (float*)d_out;

    float *A = SYM(g_A), *B = SYM(g_B), *H0 = SYM(g_H0), *SC = SYM(g_SC);
    float *T8 = SYM(g_T8), *H1 = SYM(g_H1), *H2 = SYM(g_H2), *H3 = SYM(g_H3);
    float *PX = SYM(g_PX);
    float* sw[12] = { SYM(g_sw0), SYM(g_sw1), SYM(g_sw2), SYM(g_sw3), SYM(g_sw4),
                      SYM(g_sw5), SYM(g_sw6), SYM(g_sw7), SYM(g_sw8), SYM(g_sw9),
                      SYM(g_swlin), SYM(g_swemb) };
    const int snO[12] = {256,256,256,256,256,256,256,256,256,256,1,100};
    const int snR[12] = {27,2304,3,2304,2304,256,2304,2304,2304,2304,256,256};
    const int snT[12] = {1,1,1,1,1,1,1,1,1,1,0,0};

    SnArgs sa;
    for (int i = 0; i < 12; i++)
        sa.d[i] = SnDesc{ w_raw[i], sw[i], snO[i], snR[i], snT[i] };

    init_zero_k<<<4, 256>>>();
    sn_sigma_k<<<12, 256>>>(sa);
    sn_scale_k<<<dim3(12, 64), 256>>>(sa);

    // ---- block 0 (preact=False, down) ----
    conv3x3_k<4,32,1><<<dim3(4, 8, 64), 256>>>(x,  sw[0], b0_b1, nullptr, A, 3,   256, 32, 32, 0);
    conv3x3_k<4,32,1><<<dim3(4, 8, 64), 256>>>(A,  sw[1], b0_b2, nullptr, B, 256, 256, 32, 32, 1);
    pool_k<<<192, 256>>>(x, nullptr, PX, 64*3*16*16, 16, 16);
    conv1x1_k<<<dim3(4, 128), 256>>>(PX, sw[2], b0_bsc, SC, 3, 256, 256);
    pool_k<<<16384, 256>>>(B, SC, H0, 64*256*16*16, 16, 16);

    // VQ helper sequence (inline)
    // VQ0 on H0, HW=256, N=16384
    enorm_k<<<4, 256>>>(cb0);
    xnorm_k<<<64, 256>>>(H0, 256, 256);
    vq_pass1_k<<<dim3(16, 128), 256>>>(H0, cb0, 256, 256, 1024);
    vq_pass2_k<<<64, 256>>>(16384);
    vq_reduce_k<<<64, 256>>>(256, 256);

    // ---- block 1 (preact=True, down) ----
    conv3x3_k<4,16,2><<<dim3(4, 4, 32), 256>>>(H0, sw[3], b1_b1, nullptr, A, 256, 256, 16, 16, 1);
    conv3x3_k<4,16,2><<<dim3(4, 4, 32), 256>>>(A,  sw[4], b1_b2, nullptr, B, 256, 256, 16, 16, 1);
    pool_k<<<4096, 256>>>(H0, nullptr, T8, 64*256*8*8, 8, 8);
    conv1x1_k<<<dim3(4, 32), 256>>>(T8, sw[5], b1_bsc, SC, 256, 256, 64);
    pool_k<<<4096, 256>>>(B, SC, H1, 64*256*8*8, 8, 8);

    // VQ1 on H1, HW=64, N=4096
    enorm_k<<<4, 256>>>(cb1);
    xnorm_k<<<64, 256>>>(H1, 256, 64);
    vq_pass1_k<<<dim3(16, 32), 256>>>(H1, cb1, 256, 64, 1024);
    vq_pass2_k<<<16, 256>>>(4096);
    vq_reduce_k<<<64, 256>>>(64, 256);

    // ---- block 2 (preact, identity sc) ----
    conv3x3_k<8,8,2><<<dim3(4, 1, 32), 256>>>(H1, sw[6], b2_b1, nullptr, A,  256, 256, 8, 8, 1);
    conv3x3_k<8,8,2><<<dim3(4, 1, 32), 256>>>(A,  sw[7], b2_b2, H1,      H2, 256, 256, 8, 8, 1);

    enorm_k<<<4, 256>>>(cb2);
    xnorm_k<<<64, 256>>>(H2, 256, 64);
    vq_pass1_k<<<dim3(16, 32), 256>>>(H2, cb2, 256, 64, 1024);
    vq_pass2_k<<<16, 256>>>(4096);
    vq_reduce_k<<<64, 256>>>(64, 256);

    // ---- block 3 (preact, identity sc) ----
    conv3x3_k<8,8,2><<<dim3(4, 1, 32), 256>>>(H2, sw[8], b3_b1, nullptr, A,  256, 256, 8, 8, 1);
    conv3x3_k<8,8,2><<<dim3(4, 1, 32), 256>>>(A,  sw[9], b3_b2, H2,      H3, 256, 256, 8, 8, 1);

    // VQ3 on H3 (+hist for ppl)
    enorm_k<<<4, 256>>>(cb3);
    xnorm_k<<<64, 256>>>(H3, 256, 64);
    vq_pass1_k<<<dim3(16, 32), 256>>>(H3, cb3, 256, 64, 1024);
    vq_pass2_k<<<16, 256>>>(4096);
    vq_hist_k<<<16, 256>>>(4096);
    vq_reduce_k<<<64, 256>>>(64, 256);

    // ---- head ----
    hf_k<<<64, 256>>>(H3);
    final_k<<<64, 256>>>(y, lin_b, dout);
    ppl_k<<<1, 256>>>(dout, 4096);
}

// round 3
// speedup vs baseline: 1.1113x; 1.1113x over previous
#include <cuda_runtime.h>
#include <math.h>

// ---------------- f32x2 helpers ----------------
typedef unsigned long long ull;
__device__ __forceinline__ ull pk2(float lo, float hi) {
    ull r; asm("mov.b64 %0,{%1,%2};" : "=l"(r) : "f"(lo), "f"(hi)); return r;
}
__device__ __forceinline__ void upk2(float& lo, float& hi, ull v) {
    asm("mov.b64 {%0,%1},%2;" : "=f"(lo), "=f"(hi) : "l"(v));
}
__device__ __forceinline__ ull fma2(ull a, ull b, ull c) {
    ull d; asm("fma.rn.f32x2 %0,%1,%2,%3;" : "=l"(d) : "l"(a), "l"(b), "l"(c)); return d;
}

// ---------------- static device scratch ----------------
__device__ float g_A[64u*256u*32u*32u];
__device__ float g_B[64u*256u*32u*32u];
__device__ float g_H0[64u*256u*16u*16u];
__device__ float g_SC[64u*256u*16u*16u];
__device__ float g_T8[64u*256u*8u*8u];
__device__ float g_H1[64u*256u*8u*8u];
__device__ float g_H2[64u*256u*8u*8u];
__device__ float g_H3[64u*256u*8u*8u];
__device__ float g_PX[64u*3u*16u*16u];

__device__ float g_sw0[6912];     // b0_w1  [(c*9+k)][256]
__device__ float g_sw1[589824];   // b0_w2
__device__ float g_sw2[768];      // b0_wsc [c][256]
__device__ float g_sw3[589824];   // b1_w1
__device__ float g_sw4[589824];   // b1_w2
__device__ float g_sw5[65536];    // b1_wsc
__device__ float g_sw6[589824];   // b2_w1
__device__ float g_sw7[589824];   // b2_w2
__device__ float g_sw8[589824];   // b3_w1
__device__ float g_sw9[589824];   // b3_w2
__device__ float g_swlin[256];
__device__ float g_swemb[25600];

__device__ float g_sigma[12];
__device__ float g_enorm[1024];
__device__ float2 g_cand[16384*16];
__device__ float g_xnorm[16384];
__device__ float g_md[16384];
__device__ int   g_ind[16384];
__device__ float g_qloss[64];
__device__ int   g_hist[1024];
__device__ float g_hf[64*256];

// ---------------- spectral norm ----------------
struct SnDesc { const float* w; float* out; int O; int R; int transpose; };
struct SnArgs { SnDesc d[12]; };

__global__ void init_zero_k() {
    int i = blockIdx.x * blockDim.x + threadIdx.x;
    if (i < 1024) g_hist[i] = 0;
    if (i < 64)   g_qloss[i] = 0.f;
}

__global__ void sn_sigma_k(SnArgs a) {
    __shared__ float sv[2304];
    __shared__ float red[256];
    const SnDesc d = a.d[blockIdx.x];
    const float* W = d.w;
    const int O = d.O, R = d.R, tid = threadIdx.x;
    const float is = rsqrtf((float)O);
    for (int j = tid; j < R; j += 256) {
        float s = 0.f;
        for (int i = 0; i < O; i++) s += W[(size_t)i * R + j];
        sv[j] = s * is;
    }
    __syncthreads();
    float loc = 0.f;
    for (int j = tid; j < R; j += 256) { float v = sv[j]; loc += v * v; }
    red[tid] = loc; __syncthreads();
    for (int s = 128; s > 0; s >>= 1) { if (tid < s) red[tid] += red[tid + s]; __syncthreads(); }
    const float fv = 1.f / (sqrtf(red[0]) + 1e-8f);
    __syncthreads();
    loc = 0.f;
    for (int i = tid; i < O; i += 256) {
        float t = 0.f;
        const float* row = W + (size_t)i * R;
        for (int j = 0; j < R; j++) t += row[j] * sv[j];
        t *= fv; loc += t * t;
    }
    red[tid] = loc; __syncthreads();
    for (int s = 128; s > 0; s >>= 1) { if (tid < s) red[tid] += red[tid + s]; __syncthreads(); }
    if (tid == 0) g_sigma[blockIdx.x] = red[0] / (sqrtf(red[0]) + 1e-8f);
}

__global__ void sn_scale_k(SnArgs a) {
    const SnDesc d = a.d[blockIdx.x];
    const float inv = 1.f / g_sigma[blockIdx.x];
    const int n = d.O * d.R, stride = gridDim.y * blockDim.x;
    for (int e = blockIdx.y * blockDim.x + threadIdx.x; e < n; e += stride) {
        float v = d.w[e] * inv;
        if (d.transpose) { int o = e / d.R, rr = e % d.R; d.out[(size_t)rr * d.O + o] = v; }
        else d.out[e] = v;
    }
}

// ---------------- conv3x3 pad1, f32x2 over output-channel pairs ----------------
// 8 warps; warp ot owns outputs o = obase + ot*8 + [0..8); lanes = pixels (4 px each).
template<int TH, int TW, int G>
__global__ void __launch_bounds__(256) conv3x3_k(
    const float* __restrict__ in, const float* __restrict__ wt,
    const float* __restrict__ bias, const float* __restrict__ res,
    float* __restrict__ out, int C, int O, int H, int W, int relu_in)
{
    constexpr int PH = TH + 2, PW = TW + 4, XG = TW / 4;
    __shared__ __align__(16) float s_in[G * PH * PW];
    __shared__ __align__(16) float s_w2[576];   // [pair 0..31][k 0..8][2]
    const int tid = threadIdx.x, ot = tid >> 5, pt = tid & 31;
    const int g = pt / (TH * XG), r = pt % (TH * XG), row = r / XG, xg = r % XG;
    const int tilesX = W / TW;
    const int tileY = blockIdx.y / tilesX, tileX = blockIdx.y % tilesX;
    const int img = blockIdx.z * G + g, obase = blockIdx.x * 64;

    ull acc2[4][4];   // [pair p][px], lanes = (o=2p, o=2p+1)
#pragma unroll
    for (int p = 0; p < 4; p++)
#pragma unroll
        for (int px = 0; px < 4; px++) acc2[p][px] = 0ull;

    for (int c = 0; c < C; c++) {
        __syncthreads();
        for (int idx = tid; idx < G * PH * (TW + 2); idx += 256) {
            int gg = idx / (PH * (TW + 2));
            int r2 = idx % (PH * (TW + 2));
            int py = r2 / (TW + 2), px = r2 % (TW + 2);
            int gy = tileY * TH + py - 1, gx = tileX * TW + px - 1;
            float v = 0.f;
            if ((unsigned)gy < (unsigned)H && (unsigned)gx < (unsigned)W)
                v = in[(((size_t)(blockIdx.z * G + gg) * C + c) * H + gy) * W + gx];
            if (relu_in) v = fmaxf(v, 0.f);
            s_in[gg * PH * PW + py * PW + px] = v;
        }
        for (int idx = tid; idx < 576; idx += 256) {
            int k = idx >> 6, o = idx & 63;
            s_w2[(o >> 1) * 18 + k * 2 + (o & 1)] = wt[((size_t)c * 9 + k) * O + obase + o];
        }
        __syncthreads();

        const float* sp = &s_in[g * PH * PW + row * PW + xg * 4];
        const ull* wp = (const ull*)&s_w2[ot * 4 * 18];   // 4 pairs x 9 k (ull each)
#pragma unroll
        for (int dy = 0; dy < 3; dy++) {
            float4 v4 = *(const float4*)(sp + dy * PW);
            float2 v2 = *(const float2*)(sp + dy * PW + 4);
            ull ivb[6];
            ivb[0] = pk2(v4.x, v4.x); ivb[1] = pk2(v4.y, v4.y);
            ivb[2] = pk2(v4.z, v4.z); ivb[3] = pk2(v4.w, v4.w);
            ivb[4] = pk2(v2.x, v2.x); ivb[5] = pk2(v2.y, v2.y);
#pragma unroll
            for (int dx = 0; dx < 3; dx++) {
                const int k = dy * 3 + dx;
#pragma unroll
                for (int p = 0; p < 4; p++) {
                    ull w = wp[p * 9 + k];
                    acc2[p][0] = fma2(w, ivb[dx + 0], acc2[p][0]);
                    acc2[p][1] = fma2(w, ivb[dx + 1], acc2[p][1]);
                    acc2[p][2] = fma2(w, ivb[dx + 2], acc2[p][2]);
                    acc2[p][3] = fma2(w, ivb[dx + 3], acc2[p][3]);
                }
            }
        }
    }

    const int y = tileY * TH + row, x = tileX * TW + xg * 4;
#pragma unroll
    for (int p = 0; p < 4; p++) {
        float lo0, hi0, lo1, hi1, lo2, hi2, lo3, hi3;
        upk2(lo0, hi0, acc2[p][0]); upk2(lo1, hi1, acc2[p][1]);
        upk2(lo2, hi2, acc2[p][2]); upk2(lo3, hi3, acc2[p][3]);
        int o0 = obase + ot * 8 + 2 * p;
        float b0 = bias[o0], b1 = bias[o0 + 1];
        size_t base0 = (((size_t)img * O + o0) * H + y) * W + x;
        size_t base1 = base0 + (size_t)H * W;
        float4 v0 = { lo0 + b0, lo1 + b0, lo2 + b0, lo3 + b0 };
        float4 v1 = { hi0 + b1, hi1 + b1, hi2 + b1, hi3 + b1 };
        if (res) {
            float4 r0 = *reinterpret_cast<const float4*>(res + base0);
            float4 r1 = *reinterpret_cast<const float4*>(res + base1);
            v0.x += r0.x; v0.y += r0.y; v0.z += r0.z; v0.w += r0.w;
            v1.x += r1.x; v1.y += r1.y; v1.z += r1.z; v1.w += r1.w;
        }
        *reinterpret_cast<float4*>(out + base0) = v0;
        *reinterpret_cast<float4*>(out + base1) = v1;
    }
}

// ---------------- conv1x1 (scalar; tiny share of runtime) ----------------
__global__ void __launch_bounds__(256) conv1x1_k(
    const float* __restrict__ in, const float* __restrict__ wt,
    const float* __restrict__ bias, float* __restrict__ out, int C, int O, int HW)
{
    __shared__ __align__(16) float s_x[128];
    __shared__ float s_w1[64];
    const int tid = threadIdx.x, ot = tid >> 5, pt = tid & 31;
    const int obase = blockIdx.x * 64, pbase = blockIdx.y * 128;
    float acc[8][4];
#pragma unroll
    for (int a = 0; a < 8; a++) { acc[a][0]=acc[a][1]=acc[a][2]=acc[a][3]=0.f; }
    for (int c = 0; c < C; c++) {
        __syncthreads();
        if (tid < 128) {
            int p = pbase + tid, b = p / HW, hw = p % HW;
            s_x[tid] = in[((size_t)b * C + c) * HW + hw];
        } else if (tid < 192) s_w1[tid - 128] = wt[(size_t)c * O + obase + (tid - 128)];
        __syncthreads();
        float4 xv = *reinterpret_cast<const float4*>(&s_x[pt * 4]);
#pragma unroll
        for (int oo = 0; oo < 8; oo++) {
            float w = s_w1[oo * 8 + ot];
            acc[oo][0] += w * xv.x; acc[oo][1] += w * xv.y;
            acc[oo][2] += w * xv.z; acc[oo][3] += w * xv.w;
        }
    }
    int p = pbase + pt * 4, b = p / HW, hw = p % HW;
#pragma unroll
    for (int oo = 0; oo < 8; oo++) {
        int o = obase + oo * 8 + ot;
        float bb = bias[o];
        float4 v = { acc[oo][0] + bb, acc[oo][1] + bb, acc[oo][2] + bb, acc[oo][3] + bb };
        *reinterpret_cast<float4*>(out + ((size_t)b * O + o) * HW + hw) = v;
    }
}

// ---------------- avgpool 2x2 (+res) ----------------
__global__ void pool_k(const float* __restrict__ in, const float* __restrict__ res,
                       float* __restrict__ out, int total, int OH, int OW)
{
    int idx = blockIdx.x * blockDim.x + threadIdx.x;
    if (idx >= total) return;
    int ow = idx % OW, t = idx / OW, oh = t % OH, bc = t / OH;
    int IW = OW * 2;
    size_t base = (((size_t)bc * (OH * 2)) + oh * 2) * IW + ow * 2;
    float v = 0.25f * (in[base] + in[base + 1] + in[base + IW] + in[base + IW + 1]);
    if (res) v += res[idx];
    out[idx] = v;
}

// ---------------- VQ ----------------
__global__ void enorm_k(const float* __restrict__ cb) {
    int k = blockIdx.x * blockDim.x + threadIdx.x;
    if (k >= 1024) return;
    float s = 0.f;
    for (int c = 0; c < 256; c++) { float v = cb[(size_t)c * 1024 + k]; s += v * v; }
    g_enorm[k] = s;
}

__global__ void xnorm_k(const float* __restrict__ h, int C, int HW) {
    int b = blockIdx.x;
    for (int hw = threadIdx.x; hw < HW; hw += blockDim.x) {
        float s = 0.f;
        for (int c = 0; c < C; c++) { float v = h[((size_t)b * C + c) * HW + hw]; s += v * v; }
        g_xnorm[b * HW + hw] = s;
    }
}

// score s_k = x.e_k - 0.5||e_k||^2 ; warp ot owns codes k = ktile*64 + ot*8 + [0..8)
__global__ void __launch_bounds__(256) vq_pass1_k(
    const float* __restrict__ h, const float* __restrict__ cb, int C, int HW, int K)
{
    __shared__ __align__(16) float s_x[128];
    __shared__ __align__(16) float s_e[64];
    __shared__ float s_bv[1024];
    __shared__ int   s_bi[1024];
    const int tid = threadIdx.x, ot = tid >> 5, pt = tid & 31;
    const int ktile = blockIdx.x, pbase = blockIdx.y * 128;
    const int kloc = ot * 8;

    ull acc2[4][4];
#pragma unroll
    for (int p = 0; p < 4; p++) {
        int k0 = ktile * 64 + kloc + 2 * p;
        ull e = pk2(-0.5f * g_enorm[k0], -0.5f * g_enorm[k0 + 1]);
        acc2[p][0] = acc2[p][1] = acc2[p][2] = acc2[p][3] = e;
    }
    for (int c = 0; c < C; c++) {
        __syncthreads();
        if (tid < 128) {
            int p = pbase + tid, b = p / HW, hw = p % HW;
            s_x[tid] = h[((size_t)b * C + c) * HW + hw];
        } else if (tid < 192) s_e[tid - 128] = cb[(size_t)c * K + ktile * 64 + (tid - 128)];
        __syncthreads();
        float4 xv = *reinterpret_cast<const float4*>(&s_x[pt * 4]);
        ull xb0 = pk2(xv.x, xv.x), xb1 = pk2(xv.y, xv.y);
        ull xb2 = pk2(xv.z, xv.z), xb3 = pk2(xv.w, xv.w);
        const ull* ep = (const ull*)&s_e[kloc];
#pragma unroll
        for (int p = 0; p < 4; p++) {
            ull w = ep[p];
            acc2[p][0] = fma2(w, xb0, acc2[p][0]);
            acc2[p][1] = fma2(w, xb1, acc2[p][1]);
            acc2[p][2] = fma2(w, xb2, acc2[p][2]);
            acc2[p][3] = fma2(w, xb3, acc2[p][3]);
        }
    }
    __syncthreads();
#pragma unroll
    for (int pp = 0; pp < 4; pp++) {
        float bv = -1e30f; int bi = 0;
#pragma unroll
        for (int p = 0; p < 4; p++) {
            float lo, hi; upk2(lo, hi, acc2[p][pp]);
            int k0 = ktile * 64 + kloc + 2 * p;
            if (lo > bv) { bv = lo; bi = k0; }
            if (hi > bv) { bv = hi; bi = k0 + 1; }
        }
        s_bv[pp * 256 + tid] = bv; s_bi[pp * 256 + tid] = bi;
    }
    __syncthreads();
    if (tid < 32) {
#pragma unroll
        for (int pp = 0; pp < 4; pp++) {
            float bv = s_bv[pp * 256 + tid]; int bi = s_bi[pp * 256 + tid];
            for (int o2 = 1; o2 < 8; o2++) {
                float v = s_bv[pp * 256 + o2 * 32 + tid];
                if (v > bv) { bv = v; bi = s_bi[pp * 256 + o2 * 32 + tid]; }
            }
            int p = pbase + tid * 4 + pp;
            g_cand[(size_t)p * 16 + ktile] = make_float2(bv, __int_as_float(bi));
        }
    }
}

__global__ void vq_pass2_k(int N) {
    int n = blockIdx.x * blockDim.x + threadIdx.x;
    if (n >= N) return;
    float2 c0 = g_cand[(size_t)n * 16];
    float bv = c0.x; int bi = __float_as_int(c0.y);
    for (int t = 1; t < 16; t++) {
        float2 ct = g_cand[(size_t)n * 16 + t];
        if (ct.x > bv) { bv = ct.x; bi = __float_as_int(ct.y); }
    }
    g_md[n] = g_xnorm[n] - 2.f * bv;
    g_ind[n] = bi;
}

__global__ void vq_hist_k(int N) {
    int n = blockIdx.x * blockDim.x + threadIdx.x;
    if (n < N) atomicAdd(&g_hist[g_ind[n]], 1);
}

__global__ void vq_reduce_k(int HW, int C) {
    __shared__ float red[256];
    int b = blockIdx.x;
    float s = 0.f;
    for (int hw = threadIdx.x; hw < HW; hw += 256) s += g_md[b * HW + hw];
    red[threadIdx.x] = s; __syncthreads();
    for (int st = 128; st > 0; st >>= 1) {
        if (threadIdx.x < st) red[threadIdx.x] += red[threadIdx.x + st];
        __syncthreads();
    }
    if (threadIdx.x == 0) g_qloss[b] += 0.5f * red[0] / ((float)HW * (float)C);
}

__global__ void ppl_k(float* __restrict__ dout, int N) {
    __shared__ float red[256];
    float s = 0.f;
    for (int k = threadIdx.x; k < 1024; k += 256) {
        float p = (float)g_hist[k] / (float)N;
        s += p * logf(p + 1e-10f);
    }
    red[threadIdx.x] = s; __syncthreads();
    for (int st = 128; st > 0; st >>= 1) {
        if (threadIdx.x < st) red[threadIdx.x] += red[threadIdx.x + st];
        __syncthreads();
    }
    if (threadIdx.x == 0) dout[128] = expf(-red[0]);
}

// ---------------- head ----------------
__global__ void hf_k(const float* __restrict__ h) {
    int idx = blockIdx.x * blockDim.x + threadIdx.x;
    if (idx >= 64 * 256) return;
    const float* p = h + (size_t)idx * 64;
    float s = 0.f;
    for (int i = 0; i < 64; i++) s += fmaxf(p[i], 0.f);
    g_hf[idx] = s;
}

__global__ void final_k(const int* __restrict__ y, const float* __restrict__ lin_b,
                        float* __restrict__ dout) {
    __shared__ float red[256];
    int b = blockIdx.x, c = threadIdx.x;
    float v = g_hf[b * 256 + c];
    red[c] = v * g_swlin[c] + v * g_swemb[(size_t)y[b] * 256 + c];
    __syncthreads();
    for (int st = 128; st > 0; st >>= 1) {
        if (c < st) red[c] += red[c + st];
        __syncthreads();
    }
    if (c == 0) { dout[b] = red[0] + lin_b[0]; dout[64 + b] = g_qloss[b]; }
}

// ---------------- host ----------------
#define SYM(x) ([]{ void* p=nullptr; cudaGetSymbolAddress(&p, x); return (float*)p; }())

extern "C" void kernel_launch(void* const* d_in, const int* in_sizes, int n_in,
                              void* d_out, int out_size) {
    (void)in_sizes; (void)n_in; (void)out_size;
    const float* x      = (const float*)d_in[0];
    const int*   y      = (const int*)d_in[1];
    const float* w_raw[12] = {
        (const float*)d_in[2],  (const float*)d_in[4],  (const float*)d_in[6],
        (const float*)d_in[8],  (const float*)d_in[10], (const float*)d_in[12],
        (const float*)d_in[14], (const float*)d_in[16], (const float*)d_in[18],
        (const float*)d_in[20], (const float*)d_in[26], (const float*)d_in[28] };
    const float* b0_b1 = (const float*)d_in[3],  *b0_b2 = (const float*)d_in[5];
    const float* b0_bsc= (const float*)d_in[7],  *b1_b1 = (const float*)d_in[9];
    const float* b1_b2 = (const float*)d_in[11], *b1_bsc= (const float*)d_in[13];
    const float* b2_b1 = (const float*)d_in[15], *b2_b2 = (const float*)d_in[17];
    const float* b3_b1 = (const float*)d_in[19], *b3_b2 = (const float*)d_in[21];
    const float* cb0 = (const float*)d_in[22], *cb1 = (const float*)d_in[23];
    const float* cb2 = (const float*)d_in[24], *cb3 = (const float*)d_in[25];
    const float* lin_b = (const float*)d_in[27];
    float* dout = (float*)d_out;

    float *A = SYM(g_A), *B = SYM(g_B), *H0 = SYM(g_H0), *SC = SYM(g_SC);
    float *T8 = SYM(g_T8), *H1 = SYM(g_H1), *H2 = SYM(g_H2), *H3 = SYM(g_H3);
    float *PX = SYM(g_PX);
    float* sw[12] = { SYM(g_sw0), SYM(g_sw1), SYM(g_sw2), SYM(g_sw3), SYM(g_sw4),
                      SYM(g_sw5), SYM(g_sw6), SYM(g_sw7), SYM(g_sw8), SYM(g_sw9),
                      SYM(g_swlin), SYM(g_swemb) };
    const int snO[12] = {256,256,256,256,256,256,256,256,256,256,1,100};
    const int snR[12] = {27,2304,3,2304,2304,256,2304,2304,2304,2304,256,256};
    const int snT[12] = {1,1,1,1,1,1,1,1,1,1,0,0};

    SnArgs sa;
    for (int i = 0; i < 12; i++)
        sa.d[i] = SnDesc{ w_raw[i], sw[i], snO[i], snR[i], snT[i] };

    init_zero_k<<<4, 256>>>();
    sn_sigma_k<<<12, 256>>>(sa);
    sn_scale_k<<<dim3(12, 64), 256>>>(sa);

    // ---- block 0 (preact=False, down) ----
    conv3x3_k<4,32,1><<<dim3(4, 8, 64), 256>>>(x,  sw[0], b0_b1, nullptr, A, 3,   256, 32, 32, 0);
    conv3x3_k<4,32,1><<<dim3(4, 8, 64), 256>>>(A,  sw[1], b0_b2, nullptr, B, 256, 256, 32, 32, 1);
    pool_k<<<192, 256>>>(x, nullptr, PX, 64*3*16*16, 16, 16);
    conv1x1_k<<<dim3(4, 128), 256>>>(PX, sw[2], b0_bsc, SC, 3, 256, 256);
    pool_k<<<16384, 256>>>(B, SC, H0, 64*256*16*16, 16, 16);

    // VQ0 on H0, HW=256, N=16384
    enorm_k<<<4, 256>>>(cb0);
    xnorm_k<<<64, 256>>>(H0, 256, 256);
    vq_pass1_k<<<dim3(16, 128), 256>>>(H0, cb0, 256, 256, 1024);
    vq_pass2_k<<<64, 256>>>(16384);
    vq_reduce_k<<<64, 256>>>(256, 256);

    // ---- block 1 (preact=True, down) ----
    conv3x3_k<4,16,2><<<dim3(4, 4, 32), 256>>>(H0, sw[3], b1_b1, nullptr, A, 256, 256, 16, 16, 1);
    conv3x3_k<4,16,2><<<dim3(4, 4, 32), 256>>>(A,  sw[4], b1_b2, nullptr, B, 256, 256, 16, 16, 1);
    pool_k<<<4096, 256>>>(H0, nullptr, T8, 64*256*8*8, 8, 8);
    conv1x1_k<<<dim3(4, 32), 256>>>(T8, sw[5], b1_bsc, SC, 256, 256, 64);
    pool_k<<<4096, 256>>>(B, SC, H1, 64*256*8*8, 8, 8);

    // VQ1 on H1, HW=64, N=4096
    enorm_k<<<4, 256>>>(cb1);
    xnorm_k<<<64, 256>>>(H1, 256, 64);
    vq_pass1_k<<<dim3(16, 32), 256>>>(H1, cb1, 256, 64, 1024);
    vq_pass2_k<<<16, 256>>>(4096);
    vq_reduce_k<<<64, 256>>>(64, 256);

    // ---- block 2 (preact, identity sc) ----
    conv3x3_k<8,8,2><<<dim3(4, 1, 32), 256>>>(H1, sw[6], b2_b1, nullptr, A,  256, 256, 8, 8, 1);
    conv3x3_k<8,8,2><<<dim3(4, 1, 32), 256>>>(A,  sw[7], b2_b2, H1,      H2, 256, 256, 8, 8, 1);

    enorm_k<<<4, 256>>>(cb2);
    xnorm_k<<<64, 256>>>(H2, 256, 64);
    vq_pass1_k<<<dim3(16, 32), 256>>>(H2, cb2, 256, 64, 1024);
    vq_pass2_k<<<16, 256>>>(4096);
    vq_reduce_k<<<64, 256>>>(64, 256);

    // ---- block 3 (preact, identity sc) ----
    conv3x3_k<8,8,2><<<dim3(4, 1, 32), 256>>>(H2, sw[8], b3_b1, nullptr, A,  256, 256, 8, 8, 1);
    conv3x3_k<8,8,2><<<dim3(4, 1, 32), 256>>>(A,  sw[9], b3_b2, H2,      H3, 256, 256, 8, 8, 1);

    // VQ3 on H3 (+hist for ppl)
    enorm_k<<<4, 256>>>(cb3);
    xnorm_k<<<64, 256>>>(H3, 256, 64);
    vq_pass1_k<<<dim3(16, 32), 256>>>(H3, cb3, 256, 64, 1024);
    vq_pass2_k<<<16, 256>>>(4096);
    vq_hist_k<<<16, 256>>>(4096);
    vq_reduce_k<<<64, 256>>>(64, 256);

    // ---- head ----
    hf_k<<<64, 256>>>(H3);
    final_k<<<64, 256>>>(y, lin_b, dout);
    ppl_k<<<1, 256>>>(dout, 4096);
}

// round 4
// speedup vs baseline: 1.5057x; 1.3550x over previous
#include <cuda_runtime.h>
#include <math.h>

// ---------------- f32x2 helpers ----------------
typedef unsigned long long ull;
__device__ __forceinline__ ull pk2(float lo, float hi) {
    ull r; asm("mov.b64 %0,{%1,%2};" : "=l"(r) : "f"(lo), "f"(hi)); return r;
}
__device__ __forceinline__ void upk2(float& lo, float& hi, ull v) {
    asm("mov.b64 {%0,%1},%2;" : "=f"(lo), "=f"(hi) : "l"(v));
}
__device__ __forceinline__ ull fma2(ull a, ull b, ull c) {
    ull d; asm("fma.rn.f32x2 %0,%1,%2,%3;" : "=l"(d) : "l"(a), "l"(b), "l"(c)); return d;
}

// ---------------- static device scratch ----------------
__device__ float g_A[64u*256u*32u*32u];
__device__ float g_B[64u*256u*32u*32u];
__device__ float g_H0[64u*256u*16u*16u];
__device__ float g_SC[64u*256u*16u*16u];
__device__ float g_T8[64u*256u*8u*8u];
__device__ float g_H1[64u*256u*8u*8u];
__device__ float g_H2[64u*256u*8u*8u];
__device__ float g_H3[64u*256u*8u*8u];
__device__ float g_PX[64u*3u*16u*16u];

__device__ float g_sw0[6912];     // b0_w1  [(c*9+k)][256]
__device__ float g_sw1[589824];   // b0_w2
__device__ float g_sw2[768];      // b0_wsc [c][256]
__device__ float g_sw3[589824];   // b1_w1
__device__ float g_sw4[589824];   // b1_w2
__device__ float g_sw5[65536];    // b1_wsc
__device__ float g_sw6[589824];   // b2_w1
__device__ float g_sw7[589824];   // b2_w2
__device__ float g_sw8[589824];   // b3_w1
__device__ float g_sw9[589824];   // b3_w2
__device__ float g_swlin[256];
__device__ float g_swemb[25600];

__device__ float g_sigma[12];
__device__ float g_enorm[1024];
__device__ float2 g_cand[16384*16];
__device__ float g_xnorm[16384];
__device__ float g_md[16384];
__device__ int   g_ind[16384];
__device__ float g_qloss[64];
__device__ int   g_hist[1024];
__device__ float g_hf[64*256];

// ---------------- spectral norm ----------------
struct SnDesc { const float* w; float* out; int O; int R; int transpose; };
struct SnArgs { SnDesc d[12]; };

__global__ void init_zero_k() {
    int i = blockIdx.x * blockDim.x + threadIdx.x;
    if (i < 1024) g_hist[i] = 0;
    if (i < 64)   g_qloss[i] = 0.f;
}

__global__ void sn_sigma_k(SnArgs a) {
    __shared__ float sv[2304];
    __shared__ float red[256];
    const SnDesc d = a.d[blockIdx.x];
    const float* W = d.w;
    const int O = d.O, R = d.R, tid = threadIdx.x;
    const int wid = tid >> 5, lane = tid & 31;
    const float is = rsqrtf((float)O);

    // v = W^T u (column sums), coalesced across tid
    for (int j = tid; j < R; j += 256) {
        float s = 0.f;
#pragma unroll 4
        for (int i = 0; i < O; i++) s += W[(size_t)i * R + j];
        sv[j] = s * is;
    }
    __syncthreads();
    float loc = 0.f;
    for (int j = tid; j < R; j += 256) { float v = sv[j]; loc += v * v; }
    red[tid] = loc; __syncthreads();
    for (int s = 128; s > 0; s >>= 1) { if (tid < s) red[tid] += red[tid + s]; __syncthreads(); }
    const float fv = 1.f / (sqrtf(red[0]) + 1e-8f);
    __syncthreads();

    // t = W v_hat, warp-per-row (lanes coalesced over columns)
    loc = 0.f;
    for (int i = wid; i < O; i += 8) {
        float t = 0.f;
        const float* row = W + (size_t)i * R;
        for (int j = lane; j < R; j += 32) t += row[j] * sv[j];
#pragma unroll
        for (int off = 16; off; off >>= 1) t += __shfl_xor_sync(0xffffffffu, t, off);
        t *= fv;
        if (lane == 0) loc += t * t;
    }
    red[tid] = loc; __syncthreads();
    for (int s = 128; s > 0; s >>= 1) { if (tid < s) red[tid] += red[tid + s]; __syncthreads(); }
    if (tid == 0) g_sigma[blockIdx.x] = red[0] / (sqrtf(red[0]) + 1e-8f);
}

__global__ void sn_scale_k(SnArgs a) {
    const SnDesc d = a.d[blockIdx.x];
    const float inv = 1.f / g_sigma[blockIdx.x];
    const int n = d.O * d.R, stride = gridDim.y * blockDim.x;
    for (int e = blockIdx.y * blockDim.x + threadIdx.x; e < n; e += stride) {
        float v = d.w[e] * inv;
        if (d.transpose) { int o = e / d.R, rr = e % d.R; d.out[(size_t)rr * d.O + o] = v; }
        else d.out[e] = v;
    }
}

// ---------------- conv3x3 pad1, f32x2, NC channels per barrier stage ----------------
template<int TH, int TW, int G, int NC>
__global__ void __launch_bounds__(256) conv3x3_k(
    const float* __restrict__ in, const float* __restrict__ wt,
    const float* __restrict__ bias, const float* __restrict__ res,
    float* __restrict__ out, int C, int O, int H, int W, int relu_in)
{
    constexpr int PH = TH + 2, PW = TW + 4, XG = TW / 4;
    constexpr int SROW = TW + 2;
    __shared__ __align__(16) float s_in[NC * G * PH * PW];
    __shared__ __align__(16) float s_w2[NC * 576];
    const int tid = threadIdx.x, ot = tid >> 5, pt = tid & 31;
    const int g = pt / (TH * XG), r = pt % (TH * XG), row = r / XG, xg = r % XG;
    const int tilesX = W / TW;
    const int tileY = blockIdx.y / tilesX, tileX = blockIdx.y % tilesX;
    const int img = blockIdx.z * G + g, obase = blockIdx.x * 64;

    ull acc2[4][4];
#pragma unroll
    for (int p = 0; p < 4; p++)
#pragma unroll
        for (int px = 0; px < 4; px++) acc2[p][px] = 0ull;

    for (int c0 = 0; c0 < C; c0 += NC) {
        __syncthreads();
        // stage NC channels of input (batched LDGs -> high MLP)
        for (int idx = tid; idx < NC * G * PH * SROW; idx += 256) {
            int cc = idx / (G * PH * SROW);
            int r3 = idx % (G * PH * SROW);
            int gg = r3 / (PH * SROW);
            int r2 = r3 % (PH * SROW);
            int py = r2 / SROW, px = r2 % SROW;
            int gy = tileY * TH + py - 1, gx = tileX * TW + px - 1;
            float v = 0.f;
            if ((unsigned)gy < (unsigned)H && (unsigned)gx < (unsigned)W)
                v = in[(((size_t)(blockIdx.z * G + gg) * C + c0 + cc) * H + gy) * W + gx];
            if (relu_in) v = fmaxf(v, 0.f);
            s_in[(cc * G + gg) * PH * PW + py * PW + px] = v;
        }
        // stage NC channels of weights, pair-interleaved per warp
        for (int idx = tid; idx < NC * 576; idx += 256) {
            int cc = idx / 576, r2 = idx % 576;
            int k = r2 >> 6, o = r2 & 63;
            s_w2[cc * 576 + (o >> 1) * 18 + k * 2 + (o & 1)] =
                wt[((size_t)(c0 + cc) * 9 + k) * O + obase + o];
        }
        __syncthreads();

#pragma unroll 1
        for (int cc = 0; cc < NC; cc++) {
            const float* sp = &s_in[(cc * G + g) * PH * PW + row * PW + xg * 4];
            const ull* wp = (const ull*)&s_w2[cc * 576 + ot * 72];
#pragma unroll
            for (int dy = 0; dy < 3; dy++) {
                float4 v4 = *(const float4*)(sp + dy * PW);
                float2 v2 = *(const float2*)(sp + dy * PW + 4);
                ull ivb[6];
                ivb[0] = pk2(v4.x, v4.x); ivb[1] = pk2(v4.y, v4.y);
                ivb[2] = pk2(v4.z, v4.z); ivb[3] = pk2(v4.w, v4.w);
                ivb[4] = pk2(v2.x, v2.x); ivb[5] = pk2(v2.y, v2.y);
#pragma unroll
                for (int dx = 0; dx < 3; dx++) {
                    const int k = dy * 3 + dx;
#pragma unroll
                    for (int p = 0; p < 4; p++) {
                        ull w = wp[p * 9 + k];
                        acc2[p][0] = fma2(w, ivb[dx + 0], acc2[p][0]);
                        acc2[p][1] = fma2(w, ivb[dx + 1], acc2[p][1]);
                        acc2[p][2] = fma2(w, ivb[dx + 2], acc2[p][2]);
                        acc2[p][3] = fma2(w, ivb[dx + 3], acc2[p][3]);
                    }
                }
            }
        }
    }

    const int y = tileY * TH + row, x = tileX * TW + xg * 4;
#pragma unroll
    for (int p = 0; p < 4; p++) {
        float lo0, hi0, lo1, hi1, lo2, hi2, lo3, hi3;
        upk2(lo0, hi0, acc2[p][0]); upk2(lo1, hi1, acc2[p][1]);
        upk2(lo2, hi2, acc2[p][2]); upk2(lo3, hi3, acc2[p][3]);
        int o0 = obase + ot * 8 + 2 * p;
        float b0 = bias[o0], b1 = bias[o0 + 1];
        size_t base0 = (((size_t)img * O + o0) * H + y) * W + x;
        size_t base1 = base0 + (size_t)H * W;
        float4 v0 = { lo0 + b0, lo1 + b0, lo2 + b0, lo3 + b0 };
        float4 v1 = { hi0 + b1, hi1 + b1, hi2 + b1, hi3 + b1 };
        if (res) {
            float4 r0 = *reinterpret_cast<const float4*>(res + base0);
            float4 r1 = *reinterpret_cast<const float4*>(res + base1);
            v0.x += r0.x; v0.y += r0.y; v0.z += r0.z; v0.w += r0.w;
            v1.x += r1.x; v1.y += r1.y; v1.z += r1.z; v1.w += r1.w;
        }
        *reinterpret_cast<float4*>(out + base0) = v0;
        *reinterpret_cast<float4*>(out + base1) = v1;
    }
}

// ---------------- conv1x1, NC channels per stage ----------------
template<int NC>
__global__ void __launch_bounds__(256) conv1x1_k(
    const float* __restrict__ in, const float* __restrict__ wt,
    const float* __restrict__ bias, float* __restrict__ out, int C, int O, int lhw)
{
    __shared__ __align__(16) float s_x[NC * 128];
    __shared__ float s_w1[NC * 64];
    const int tid = threadIdx.x, ot = tid >> 5, pt = tid & 31;
    const int obase = blockIdx.x * 64, pbase = blockIdx.y * 128;
    const int hwm = (1 << lhw) - 1;
    float acc[8][4];
#pragma unroll
    for (int a = 0; a < 8; a++) { acc[a][0]=acc[a][1]=acc[a][2]=acc[a][3]=0.f; }

    for (int c0 = 0; c0 < C; c0 += NC) {
        const int cl = (C - c0 < NC) ? (C - c0) : NC;
        __syncthreads();
        for (int idx = tid; idx < cl * 128; idx += 256) {
            int cc = idx >> 7, i = idx & 127;
            int p = pbase + i, b = p >> lhw, hw = p & hwm;
            s_x[idx] = in[(((size_t)b * C + c0 + cc) << lhw) + hw];
        }
        for (int idx = tid; idx < cl * 64; idx += 256) {
            int cc = idx >> 6, o = idx & 63;
            s_w1[idx] = wt[(size_t)(c0 + cc) * O + obase + o];
        }
        __syncthreads();
        for (int cc = 0; cc < cl; cc++) {
            float4 xv = *reinterpret_cast<const float4*>(&s_x[cc * 128 + pt * 4]);
#pragma unroll
            for (int oo = 0; oo < 8; oo++) {
                float w = s_w1[cc * 64 + oo * 8 + ot];
                acc[oo][0] += w * xv.x; acc[oo][1] += w * xv.y;
                acc[oo][2] += w * xv.z; acc[oo][3] += w * xv.w;
            }
        }
    }
    int p = pbase + pt * 4, b = p >> lhw, hw = p & hwm;
#pragma unroll
    for (int oo = 0; oo < 8; oo++) {
        int o = obase + oo * 8 + ot;
        float bb = bias[o];
        float4 v = { acc[oo][0] + bb, acc[oo][1] + bb, acc[oo][2] + bb, acc[oo][3] + bb };
        *reinterpret_cast<float4*>(out + (((size_t)b * O + o) << lhw) + hw) = v;
    }
}

// ---------------- avgpool 2x2 (+res) ----------------
__global__ void pool_k(const float* __restrict__ in, const float* __restrict__ res,
                       float* __restrict__ out, int total, int OH, int OW)
{
    int idx = blockIdx.x * blockDim.x + threadIdx.x;
    if (idx >= total) return;
    int ow = idx % OW, t = idx / OW, oh = t % OH, bc = t / OH;
    int IW = OW * 2;
    size_t base = (((size_t)bc * (OH * 2)) + oh * 2) * IW + ow * 2;
    float v = 0.25f * (in[base] + in[base + 1] + in[base + IW] + in[base + IW + 1]);
    if (res) v += res[idx];
    out[idx] = v;
}

// ---------------- VQ ----------------
__global__ void enorm_k(const float* __restrict__ cb) {
    int k = blockIdx.x * blockDim.x + threadIdx.x;
    if (k >= 1024) return;
    float s = 0.f;
#pragma unroll 4
    for (int c = 0; c < 256; c++) { float v = cb[(size_t)c * 1024 + k]; s += v * v; }
    g_enorm[k] = s;
}

__global__ void xnorm_k(const float* __restrict__ h, int lhw, int N) {
    int n = blockIdx.x * blockDim.x + threadIdx.x;
    if (n >= N) return;
    int b = n >> lhw, hw = n & ((1 << lhw) - 1);
    const float* p = h + (((size_t)b * 256) << lhw) + hw;
    const size_t st = (size_t)1 << lhw;
    float s = 0.f;
#pragma unroll 8
    for (int c = 0; c < 256; c++) { float v = p[(size_t)c * st]; s += v * v; }
    g_xnorm[n] = s;
}

// score s_k = x.e_k - 0.5||e_k||^2 ; NC channels per stage
template<int NC>
__global__ void __launch_bounds__(256) vq_pass1_k(
    const float* __restrict__ h, const float* __restrict__ cb, int C, int lhw, int K)
{
    __shared__ __align__(16) float s_x[NC * 128];
    __shared__ __align__(16) float s_e[NC * 64];
    __shared__ float s_bv[1024];
    __shared__ int   s_bi[1024];
    const int tid = threadIdx.x, ot = tid >> 5, pt = tid & 31;
    const int ktile = blockIdx.x, pbase = blockIdx.y * 128;
    const int kloc = ot * 8;
    const int hwm = (1 << lhw) - 1;

    ull acc2[4][4];
#pragma unroll
    for (int p = 0; p < 4; p++) {
        int k0 = ktile * 64 + kloc + 2 * p;
        ull e = pk2(-0.5f * g_enorm[k0], -0.5f * g_enorm[k0 + 1]);
        acc2[p][0] = acc2[p][1] = acc2[p][2] = acc2[p][3] = e;
    }
    for (int c0 = 0; c0 < C; c0 += NC) {
        __syncthreads();
        for (int idx = tid; idx < NC * 128; idx += 256) {
            int cc = idx >> 7, i = idx & 127;
            int p = pbase + i, b = p >> lhw, hw = p & hwm;
            s_x[idx] = h[(((size_t)b * C + c0 + cc) << lhw) + hw];
        }
        for (int idx = tid; idx < NC * 64; idx += 256) {
            int cc = idx >> 6, o = idx & 63;
            s_e[idx] = cb[(size_t)(c0 + cc) * K + ktile * 64 + o];
        }
        __syncthreads();
#pragma unroll 4
        for (int cc = 0; cc < NC; cc++) {
            float4 xv = *reinterpret_cast<const float4*>(&s_x[cc * 128 + pt * 4]);
            ull xb0 = pk2(xv.x, xv.x), xb1 = pk2(xv.y, xv.y);
            ull xb2 = pk2(xv.z, xv.z), xb3 = pk2(xv.w, xv.w);
            const ull* ep = (const ull*)&s_e[cc * 64 + kloc];
#pragma unroll
            for (int p = 0; p < 4; p++) {
                ull w = ep[p];
                acc2[p][0] = fma2(w, xb0, acc2[p][0]);
                acc2[p][1] = fma2(w, xb1, acc2[p][1]);
                acc2[p][2] = fma2(w, xb2, acc2[p][2]);
                acc2[p][3] = fma2(w, xb3, acc2[p][3]);
            }
        }
    }
    __syncthreads();
#pragma unroll
    for (int pp = 0; pp < 4; pp++) {
        float bv = -1e30f; int bi = 0;
#pragma unroll
        for (int p = 0; p < 4; p++) {
            float lo, hi; upk2(lo, hi, acc2[p][pp]);
            int k0 = ktile * 64 + kloc + 2 * p;
            if (lo > bv) { bv = lo; bi = k0; }
            if (hi > bv) { bv = hi; bi = k0 + 1; }
        }
        s_bv[pp * 256 + tid] = bv; s_bi[pp * 256 + tid] = bi;
    }
    __syncthreads();
    if (tid < 32) {
#pragma unroll
        for (int pp = 0; pp < 4; pp++) {
            float bv = s_bv[pp * 256 + tid]; int bi = s_bi[pp * 256 + tid];
            for (int o2 = 1; o2 < 8; o2++) {
                float v = s_bv[pp * 256 + o2 * 32 + tid];
                if (v > bv) { bv = v; bi = s_bi[pp * 256 + o2 * 32 + tid]; }
            }
            int p = pbase + tid * 4 + pp;
            g_cand[(size_t)p * 16 + ktile] = make_float2(bv, __int_as_float(bi));
        }
    }
}

__global__ void vq_pass2_k(int N) {
    int n = blockIdx.x * blockDim.x + threadIdx.x;
    if (n >= N) return;
    float2 c0 = g_cand[(size_t)n * 16];
    float bv = c0.x; int bi = __float_as_int(c0.y);
#pragma unroll
    for (int t = 1; t < 16; t++) {
        float2 ct = g_cand[(size_t)n * 16 + t];
        if (ct.x > bv) { bv = ct.x; bi = __float_as_int(ct.y); }
    }
    g_md[n] = g_xnorm[n] - 2.f * bv;
    g_ind[n] = bi;
}

__global__ void vq_hist_k(int N) {
    int n = blockIdx.x * blockDim.x + threadIdx.x;
    if (n < N) atomicAdd(&g_hist[g_ind[n]], 1);
}

__global__ void vq_reduce_k(int HW, int C) {
    __shared__ float red[256];
    int b = blockIdx.x;
    float s = 0.f;
    for (int hw = threadIdx.x; hw < HW; hw += 256) s += g_md[b * HW + hw];
    red[threadIdx.x] = s; __syncthreads();
    for (int st = 128; st > 0; st >>= 1) {
        if (threadIdx.x < st) red[threadIdx.x] += red[threadIdx.x + st];
        __syncthreads();
    }
    if (threadIdx.x == 0) g_qloss[b] += 0.5f * red[0] / ((float)HW * (float)C);
}

__global__ void ppl_k(float* __restrict__ dout, int N) {
    __shared__ float red[256];
    float s = 0.f;
    for (int k = threadIdx.x; k < 1024; k += 256) {
        float p = (float)g_hist[k] / (float)N;
        s += p * logf(p + 1e-10f);
    }
    red[threadIdx.x] = s; __syncthreads();
    for (int st = 128; st > 0; st >>= 1) {
        if (threadIdx.x < st) red[threadIdx.x] += red[threadIdx.x + st];
        __syncthreads();
    }
    if (threadIdx.x == 0) dout[128] = expf(-red[0]);
}

// ---------------- head ----------------
__global__ void hf_k(const float* __restrict__ h) {
    int idx = blockIdx.x * blockDim.x + threadIdx.x;
    if (idx >= 64 * 256) return;
    const float* p = h + (size_t)idx * 64;
    float s = 0.f;
#pragma unroll 8
    for (int i = 0; i < 64; i++) s += fmaxf(p[i], 0.f);
    g_hf[idx] = s;
}

__global__ void final_k(const int* __restrict__ y, const float* __restrict__ lin_b,
                        float* __restrict__ dout) {
    __shared__ float red[256];
    int b = blockIdx.x, c = threadIdx.x;
    float v = g_hf[b * 256 + c];
    red[c] = v * g_swlin[c] + v * g_swemb[(size_t)y[b] * 256 + c];
    __syncthreads();
    for (int st = 128; st > 0; st >>= 1) {
        if (c < st) red[c] += red[c + st];
        __syncthreads();
    }
    if (c == 0) { dout[b] = red[0] + lin_b[0]; dout[64 + b] = g_qloss[b]; }
}

// ---------------- host ----------------
#define SYM(x) ([]{ void* p=nullptr; cudaGetSymbolAddress(&p, x); return (float*)p; }())

extern "C" void kernel_launch(void* const* d_in, const int* in_sizes, int n_in,
                              void* d_out, int out_size) {
    (void)in_sizes; (void)n_in; (void)out_size;
    const float* x      = (const float*)d_in[0];
    const int*   y      = (const int*)d_in[1];
    const float* w_raw[12] = {
        (const float*)d_in[2],  (const float*)d_in[4],  (const float*)d_in[6],
        (const float*)d_in[8],  (const float*)d_in[10], (const float*)d_in[12],
        (const float*)d_in[14], (const float*)d_in[16], (const float*)d_in[18],
        (const float*)d_in[20], (const float*)d_in[26], (const float*)d_in[28] };
    const float* b0_b1 = (const float*)d_in[3],  *b0_b2 = (const float*)d_in[5];
    const float* b0_bsc= (const float*)d_in[7],  *b1_b1 = (const float*)d_in[9];
    const float* b1_b2 = (const float*)d_in[11], *b1_bsc= (const float*)d_in[13];
    const float* b2_b1 = (const float*)d_in[15], *b2_b2 = (const float*)d_in[17];
    const float* b3_b1 = (const float*)d_in[19], *b3_b2 = (const float*)d_in[21];
    const float* cb0 = (const float*)d_in[22], *cb1 = (const float*)d_in[23];
    const float* cb2 = (const float*)d_in[24], *cb3 = (const float*)d_in[25];
    const float* lin_b = (const float*)d_in[27];
    float* dout = (float*)d_out;

    float *A = SYM(g_A), *B = SYM(g_B), *H0 = SYM(g_H0), *SC = SYM(g_SC);
    float *T8 = SYM(g_T8), *H1 = SYM(g_H1), *H2 = SYM(g_H2), *H3 = SYM(g_H3);
    float *PX = SYM(g_PX);
    float* sw[12] = { SYM(g_sw0), SYM(g_sw1), SYM(g_sw2), SYM(g_sw3), SYM(g_sw4),
                      SYM(g_sw5), SYM(g_sw6), SYM(g_sw7), SYM(g_sw8), SYM(g_sw9),
                      SYM(g_swlin), SYM(g_swemb) };
    const int snO[12] = {256,256,256,256,256,256,256,256,256,256,1,100};
    const int snR[12] = {27,2304,3,2304,2304,256,2304,2304,2304,2304,256,256};
    const int snT[12] = {1,1,1,1,1,1,1,1,1,1,0,0};

    SnArgs sa;
    for (int i = 0; i < 12; i++)
        sa.d[i] = SnDesc{ w_raw[i], sw[i], snO[i], snR[i], snT[i] };

    init_zero_k<<<4, 256>>>();
    sn_sigma_k<<<12, 256>>>(sa);
    sn_scale_k<<<dim3(12, 64), 256>>>(sa);

    // ---- block 0 (preact=False, down) ----
    conv3x3_k<4,32,1,3><<<dim3(4, 8, 64), 256>>>(x,  sw[0], b0_b1, nullptr, A, 3,   256, 32, 32, 0);
    conv3x3_k<4,32,1,8><<<dim3(4, 8, 64), 256>>>(A,  sw[1], b0_b2, nullptr, B, 256, 256, 32, 32, 1);
    pool_k<<<192, 256>>>(x, nullptr, PX, 64*3*16*16, 16, 16);
    conv1x1_k<16><<<dim3(4, 128), 256>>>(PX, sw[2], b0_bsc, SC, 3, 256, 8);
    pool_k<<<16384, 256>>>(B, SC, H0, 64*256*16*16, 16, 16);

    // VQ0 on H0, HW=256, N=16384
    enorm_k<<<4, 256>>>(cb0);
    xnorm_k<<<64, 256>>>(H0, 8, 16384);
    vq_pass1_k<16><<<dim3(16, 128), 256>>>(H0, cb0, 256, 8, 1024);
    vq_pass2_k<<<64, 256>>>(16384);
    vq_reduce_k<<<64, 256>>>(256, 256);

    // ---- block 1 (preact=True, down) ----
    conv3x3_k<4,16,2,8><<<dim3(4, 4, 32), 256>>>(H0, sw[3], b1_b1, nullptr, A, 256, 256, 16, 16, 1);
    conv3x3_k<4,16,2,8><<<dim3(4, 4, 32), 256>>>(A,  sw[4], b1_b2, nullptr, B, 256, 256, 16, 16, 1);
    pool_k<<<4096, 256>>>(H0, nullptr, T8, 64*256*8*8, 8, 8);
    conv1x1_k<16><<<dim3(4, 32), 256>>>(T8, sw[5], b1_bsc, SC, 256, 256, 6);
    pool_k<<<4096, 256>>>(B, SC, H1, 64*256*8*8, 8, 8);

    // VQ1 on H1, HW=64, N=4096
    enorm_k<<<4, 256>>>(cb1);
    xnorm_k<<<16, 256>>>(H1, 6, 4096);
    vq_pass1_k<16><<<dim3(16, 32), 256>>>(H1, cb1, 256, 6, 1024);
    vq_pass2_k<<<16, 256>>>(4096);
    vq_reduce_k<<<64, 256>>>(64, 256);

    // ---- block 2 (preact, identity sc) ----
    conv3x3_k<8,8,2,8><<<dim3(4, 1, 32), 256>>>(H1, sw[6], b2_b1, nullptr, A,  256, 256, 8, 8, 1);
    conv3x3_k<8,8,2,8><<<dim3(4, 1, 32), 256>>>(A,  sw[7], b2_b2, H1,      H2, 256, 256, 8, 8, 1);

    enorm_k<<<4, 256>>>(cb2);
    xnorm_k<<<16, 256>>>(H2, 6, 4096);
    vq_pass1_k<16><<<dim3(16, 32), 256>>>(H2, cb2, 256, 6, 1024);
    vq_pass2_k<<<16, 256>>>(4096);
    vq_reduce_k<<<64, 256>>>(64, 256);

    // ---- block 3 (preact, identity sc) ----
    conv3x3_k<8,8,2,8><<<dim3(4, 1, 32), 256>>>(H2, sw[8], b3_b1, nullptr, A,  256, 256, 8, 8, 1);
    conv3x3_k<8,8,2,8><<<dim3(4, 1, 32), 256>>>(A,  sw[9], b3_b2, H2,      H3, 256, 256, 8, 8, 1);

    // VQ3 on H3 (+hist for ppl)
    enorm_k<<<4, 256>>>(cb3);
    xnorm_k<<<16, 256>>>(H3, 6, 4096);
    vq_pass1_k<16><<<dim3(16, 32), 256>>>(H3, cb3, 256, 6, 1024);
    vq_pass2_k<<<16, 256>>>(4096);
    vq_hist_k<<<16, 256>>>(4096);
    vq_reduce_k<<<64, 256>>>(64, 256);

    // ---- head ----
    hf_k<<<64, 256>>>(H3);
    final_k<<<64, 256>>>(y, lin_b, dout);
    ppl_k<<<1, 256>>>(dout, 4096);
}